// round 1
// baseline (speedup 1.0000x reference)
#include <cuda_runtime.h>
#include <cstdint>
#include <cstddef>

#define NTX 200000
#define NCL 100000
#define NME 20000
#define NE  1000000
#define DD  64

// sums laid out sum0 | sum2 | sum1 | sum3 so the layer-1 re-zero (sum0,sum2) is one contiguous range
#define SUM0_OFF ((size_t)0)
#define SUM2_OFF ((size_t)NTX*DD)
#define SUM1_OFF ((size_t)2*NTX*DD)
#define SUM3_OFF ((size_t)2*NTX*DD + (size_t)NCL*DD)
#define SUMS_LEN ((size_t)(2*NTX+NCL+NME)*DD)

#define DEG0_OFF 0
#define DEG2_OFF (NTX)
#define DEG1_OFF (2*NTX)
#define DEG3_OFF (2*NTX+NCL)
#define DEGS_LEN (2*NTX+NCL+NME)

__device__ float g_sums[SUMS_LEN];
__device__ float g_degs[DEGS_LEN];
__device__ float g_htx[(size_t)NTX*DD];
__device__ float g_hcl[(size_t)NCL*DD];
__device__ float g_hme[(size_t)NME*DD];
__device__ float g_emb[(size_t)NTX*DD];

// ---------------------------------------------------------------------------
// zero: grid-stride float4 stores
// ---------------------------------------------------------------------------
__global__ void zero_kernel(float4* __restrict__ p, size_t n4) {
    size_t i = (size_t)blockIdx.x * blockDim.x + threadIdx.x;
    size_t stride = (size_t)gridDim.x * blockDim.x;
    float4 z = make_float4(0.f, 0.f, 0.f, 0.f);
    for (; i < n4; i += stride) p[i] = z;
}

// ---------------------------------------------------------------------------
// scatter: 16 threads per edge, each handles one float4 of the 64-float row.
// Gather from hsrc[src], vector-red into sum[dst]. Optionally count degree.
// ---------------------------------------------------------------------------
__global__ void __launch_bounds__(256) scatter_kernel(
    const int* __restrict__ src, const int* __restrict__ dst,
    const float* __restrict__ hsrc,
    float* __restrict__ sum, float* __restrict__ deg, int nedges)
{
    int t = blockIdx.x * blockDim.x + threadIdx.x;
    int e = t >> 4;
    if (e >= nedges) return;
    int c = t & 15;
    int s = __ldg(src + e);
    int d = __ldg(dst + e);
    float4 v = __ldg((const float4*)hsrc + (size_t)s * 16 + c);
    float* p = sum + (size_t)d * DD + c * 4;
    asm volatile("red.global.add.v4.f32 [%0], {%1,%2,%3,%4};"
                 :: "l"(p), "f"(v.x), "f"(v.y), "f"(v.z), "f"(v.w) : "memory");
    if (deg != nullptr && c == 0) atomicAdd(deg + d, 1.0f);
}

// ---------------------------------------------------------------------------
// combine: out[row,:] = act( sum_m scale_m(X_m[row,:]) @ W_m  + bias )
//   m==0 is the "self" term (never scaled); W0 gets W0b added at load time.
//   m>=1 are neighbor sums scaled per-row by 1/max(deg,1).
// 64x64 tile per 256-thread block; thread computes a 4x4 register tile.
// X stored transposed in smem (pad 68 keeps float4 rows 16B-aligned).
// ---------------------------------------------------------------------------
template<int NMAT, bool ACT>
__global__ void __launch_bounds__(256) combine_kernel(
    int nrows,
    const float* __restrict__ X0,
    const float* __restrict__ X1, const float* __restrict__ g1,
    const float* __restrict__ X2, const float* __restrict__ g2,
    const float* __restrict__ W0, const float* __restrict__ W0b,
    const float* __restrict__ W1,
    const float* __restrict__ W2,
    const float* __restrict__ bias0, const float* __restrict__ bias0b,
    float* __restrict__ out)
{
    __shared__ float Xs[DD][68];
    __shared__ float Ws[DD * DD];
    __shared__ float bs[DD];

    const int tid  = threadIdx.x;
    const int row0 = blockIdx.x * 64;

    if (tid < DD) {
        float b = bias0[tid];
        if (bias0b) b += bias0b[tid];
        bs[tid] = b;
    }

    float acc[4][4];
#pragma unroll
    for (int r = 0; r < 4; ++r)
#pragma unroll
        for (int j = 0; j < 4; ++j) acc[r][j] = 0.f;

    const int lr = tid >> 2;   // loader row within tile, 0..63
    const int lq = tid & 3;    // loader quad
    const int tr = tid >> 4;   // compute row group, 0..15
    const int tc = tid & 15;   // compute col group, 0..15
    const int  row_l  = row0 + lr;
    const bool lvalid = row_l < nrows;

#pragma unroll
    for (int m = 0; m < NMAT; ++m) {
        const float* X = (m == 0) ? X0 : ((m == 1) ? X1 : X2);
        const float* G = (m == 0) ? (const float*)nullptr : ((m == 1) ? g1 : g2);
        const float* W = (m == 0) ? W0 : ((m == 1) ? W1 : W2);

        // load weight tile (4096 floats), fold in W0b for the self term
#pragma unroll
        for (int i = 0; i < 4; ++i) {
            float4 w = __ldg((const float4*)W + tid + i * 256);
            if (m == 0 && W0b != nullptr) {
                float4 w2 = __ldg((const float4*)W0b + tid + i * 256);
                w.x += w2.x; w.y += w2.y; w.z += w2.z; w.w += w2.w;
            }
            ((float4*)Ws)[tid + i * 256] = w;
        }

        // load X tile transposed, applying per-row mean scale for neighbor terms
        float sc = 1.0f;
        if (G != nullptr && lvalid) sc = 1.0f / fmaxf(__ldg(G + row_l), 1.0f);
#pragma unroll
        for (int i = 0; i < 4; ++i) {
            float4 v = make_float4(0.f, 0.f, 0.f, 0.f);
            if (lvalid) v = __ldg((const float4*)(X + (size_t)row_l * DD) + lq * 4 + i);
            int k = lq * 16 + i * 4;
            Xs[k + 0][lr] = v.x * sc;
            Xs[k + 1][lr] = v.y * sc;
            Xs[k + 2][lr] = v.z * sc;
            Xs[k + 3][lr] = v.w * sc;
        }
        __syncthreads();

#pragma unroll 8
        for (int k = 0; k < DD; ++k) {
            float4 wv = *(const float4*)(&Ws[k * DD + tc * 4]);
            float4 xv = *(const float4*)(&Xs[k][tr * 4]);
            acc[0][0] += xv.x * wv.x; acc[0][1] += xv.x * wv.y;
            acc[0][2] += xv.x * wv.z; acc[0][3] += xv.x * wv.w;
            acc[1][0] += xv.y * wv.x; acc[1][1] += xv.y * wv.y;
            acc[1][2] += xv.y * wv.z; acc[1][3] += xv.y * wv.w;
            acc[2][0] += xv.z * wv.x; acc[2][1] += xv.z * wv.y;
            acc[2][2] += xv.z * wv.z; acc[2][3] += xv.z * wv.w;
            acc[3][0] += xv.w * wv.x; acc[3][1] += xv.w * wv.y;
            acc[3][2] += xv.w * wv.z; acc[3][3] += xv.w * wv.w;
        }
        __syncthreads();
    }

#pragma unroll
    for (int r = 0; r < 4; ++r) {
        int row = row0 + tr * 4 + r;
        if (row < nrows) {
            float4 o;
            o.x = acc[r][0] + bs[tc * 4 + 0];
            o.y = acc[r][1] + bs[tc * 4 + 1];
            o.z = acc[r][2] + bs[tc * 4 + 2];
            o.w = acc[r][3] + bs[tc * 4 + 3];
            if (ACT) {
                o.x = o.x > 0.f ? o.x : 0.01f * o.x;
                o.y = o.y > 0.f ? o.y : 0.01f * o.y;
                o.z = o.z > 0.f ? o.z : 0.01f * o.z;
                o.w = o.w > 0.f ? o.w : 0.01f * o.w;
            }
            *((float4*)(out + (size_t)row * DD) + tc) = o;
        }
    }
}

// ---------------------------------------------------------------------------
extern "C" void kernel_launch(void* const* d_in, const int* in_sizes, int n_in,
                              void* d_out, int out_size)
{
    const float* features     = (const float*)d_in[0];
    const float* emb_client   = (const float*)d_in[1];
    const float* emb_merchant = (const float*)d_in[2];
    const float* Ws0  = (const float*)d_in[3];
    const float* Wn0  = (const float*)d_in[4];
    const float* b0   = (const float*)d_in[5];
    const float* Ws1  = (const float*)d_in[6];
    const float* Wn1  = (const float*)d_in[7];
    const float* b1   = (const float*)d_in[8];
    const float* Wout = (const float*)d_in[9];
    const float* bout = (const float*)d_in[10];
    const int* e0s = (const int*)d_in[11];
    const int* e0d = (const int*)d_in[12];
    const int* e1s = (const int*)d_in[13];
    const int* e1d = (const int*)d_in[14];
    const int* e2s = (const int*)d_in[15];
    const int* e2d = (const int*)d_in[16];
    const int* e3s = (const int*)d_in[17];
    const int* e3d = (const int*)d_in[18];
    float* out = (float*)d_out;

    float *sums, *degs, *htx, *hcl, *hme, *emb;
    cudaGetSymbolAddress((void**)&sums, g_sums);
    cudaGetSymbolAddress((void**)&degs, g_degs);
    cudaGetSymbolAddress((void**)&htx,  g_htx);
    cudaGetSymbolAddress((void**)&hcl,  g_hcl);
    cudaGetSymbolAddress((void**)&hme,  g_hme);
    cudaGetSymbolAddress((void**)&emb,  g_emb);

    // ---- zero accumulators (layer 0 needs all sums + degrees) ----
    zero_kernel<<<2048, 256>>>((float4*)sums, SUMS_LEN / 4);
    zero_kernel<<<512, 256>>>((float4*)degs, (size_t)DEGS_LEN / 4);

    const int sblocks = (NE * 16) / 256;  // exact: 62500

    // ---- layer 0 aggregation (degree counted here, reused in layer 1) ----
    scatter_kernel<<<sblocks, 256>>>(e0s, e0d, emb_client,   sums + SUM0_OFF, degs + DEG0_OFF, NE);
    scatter_kernel<<<sblocks, 256>>>(e2s, e2d, emb_merchant, sums + SUM2_OFF, degs + DEG2_OFF, NE);
    scatter_kernel<<<sblocks, 256>>>(e1s, e1d, features,     sums + SUM1_OFF, degs + DEG1_OFF, NE);
    scatter_kernel<<<sblocks, 256>>>(e3s, e3d, features,     sums + SUM3_OFF, degs + DEG3_OFF, NE);

    // ---- layer 0 combine (+ leaky_relu) ----
    combine_kernel<3, true><<<(NTX + 63) / 64, 256>>>(NTX,
        features,
        sums + SUM0_OFF, degs + DEG0_OFF,
        sums + SUM2_OFF, degs + DEG2_OFF,
        Ws0 + 0 * 4096, Ws0 + 2 * 4096,
        Wn0 + 0 * 4096, Wn0 + 2 * 4096,
        b0 + 0 * 64, b0 + 2 * 64,
        htx);
    combine_kernel<2, true><<<(NCL + 63) / 64, 256>>>(NCL,
        emb_client,
        sums + SUM1_OFF, degs + DEG1_OFF,
        nullptr, nullptr,
        Ws0 + 1 * 4096, nullptr,
        Wn0 + 1 * 4096, nullptr,
        b0 + 1 * 64, nullptr,
        hcl);
    combine_kernel<2, true><<<(NME + 63) / 64, 256>>>(NME,
        emb_merchant,
        sums + SUM3_OFF, degs + DEG3_OFF,
        nullptr, nullptr,
        Ws0 + 3 * 4096, nullptr,
        Wn0 + 3 * 4096, nullptr,
        b0 + 3 * 64, nullptr,
        hme);

    // ---- layer 1: only tx output is needed -> only relations 0 and 2 ----
    zero_kernel<<<2048, 256>>>((float4*)sums, (size_t)2 * NTX * DD / 4);  // sum0|sum2 contiguous
    scatter_kernel<<<sblocks, 256>>>(e0s, e0d, hcl, sums + SUM0_OFF, nullptr, NE);
    scatter_kernel<<<sblocks, 256>>>(e2s, e2d, hme, sums + SUM2_OFF, nullptr, NE);

    combine_kernel<3, false><<<(NTX + 63) / 64, 256>>>(NTX,
        htx,
        sums + SUM0_OFF, degs + DEG0_OFF,
        sums + SUM2_OFF, degs + DEG2_OFF,
        Ws1 + 0 * 4096, Ws1 + 2 * 4096,
        Wn1 + 0 * 4096, Wn1 + 2 * 4096,
        b1 + 0 * 64, b1 + 2 * 64,
        emb);

    // ---- output projection ----
    combine_kernel<1, false><<<(NTX + 63) / 64, 256>>>(NTX,
        emb,
        nullptr, nullptr, nullptr, nullptr,
        Wout, nullptr, nullptr, nullptr,
        bout, nullptr,
        out);

    // ---- second output: the embedding itself ----
    if (out_size >= (int)(2 * (size_t)NTX * DD)) {
        cudaMemcpyAsync(out + (size_t)NTX * DD, emb,
                        (size_t)NTX * DD * sizeof(float),
                        cudaMemcpyDeviceToDevice);
    }
}

// round 3
// speedup vs baseline: 1.1037x; 1.1037x over previous
#include <cuda_runtime.h>
#include <cstdint>
#include <cstddef>

#define NTX 200000
#define NCL 100000
#define NME 20000
#define NE  1000000
#define DD  64

#define SUM0_OFF ((size_t)0)
#define SUM2_OFF ((size_t)NTX*DD)
#define SUM1_OFF ((size_t)2*NTX*DD)
#define SUM3_OFF ((size_t)2*NTX*DD + (size_t)NCL*DD)
#define SUMS_LEN ((size_t)(2*NTX+NCL+NME)*DD)

#define DEG0_OFF 0
#define DEG2_OFF (NTX)
#define DEG1_OFF (2*NTX)
#define DEG3_OFF (2*NTX+NCL)
#define DEGS_LEN (2*NTX+NCL+NME)

__device__ float g_sums[SUMS_LEN];
__device__ float g_degs[DEGS_LEN];
__device__ float g_htx[(size_t)NTX*DD];
__device__ float g_hcl[(size_t)NCL*DD];
__device__ float g_hme[(size_t)NME*DD];
__device__ float g_emb[(size_t)NTX*DD];

// ---------------- packed fp32x2 helpers (Blackwell FFMA2) -------------------
typedef unsigned long long u64;
__device__ __forceinline__ u64 f2pk(float lo, float hi) {
    u64 r; asm("mov.b64 %0,{%1,%2};" : "=l"(r) : "f"(lo), "f"(hi)); return r;
}
__device__ __forceinline__ void f2fma(u64& d, u64 a, u64 b) {
    asm("fma.rn.f32x2 %0,%1,%2,%0;" : "+l"(d) : "l"(a), "l"(b));
}
__device__ __forceinline__ void f2un(u64 p, float& lo, float& hi) {
    asm("mov.b64 {%0,%1},%2;" : "=f"(lo), "=f"(hi) : "l"(p));
}

// ---------------------------------------------------------------------------
__global__ void zero_kernel(float4* __restrict__ p, size_t n4) {
    size_t i = (size_t)blockIdx.x * blockDim.x + threadIdx.x;
    size_t stride = (size_t)gridDim.x * blockDim.x;
    float4 z = make_float4(0.f, 0.f, 0.f, 0.f);
    for (; i < n4; i += stride) p[i] = z;
}

// degree count: one thread per edge
__global__ void __launch_bounds__(256) deg_kernel(const int* __restrict__ dst,
                                                  float* __restrict__ deg, int n) {
    int i = blockIdx.x * blockDim.x + threadIdx.x;
    if (i < n) atomicAdd(deg + __ldg(dst + i), 1.0f);
}

// deg -> 1/max(deg,1) in place
__global__ void __launch_bounds__(256) inv_kernel(float* __restrict__ deg, int n) {
    int i = blockIdx.x * blockDim.x + threadIdx.x;
    if (i < n) deg[i] = 1.0f / fmaxf(deg[i], 1.0f);
}

// ---------------------------------------------------------------------------
// scatter: 16 threads per edge slot, 2 independent edges per thread (MLP).
// NE is even; grid covers NE/2 edge slots exactly.
// ---------------------------------------------------------------------------
__device__ __forceinline__ void red4(float* p, float4 v) {
    asm volatile("red.global.add.v4.f32 [%0], {%1,%2,%3,%4};"
                 :: "l"(p), "f"(v.x), "f"(v.y), "f"(v.z), "f"(v.w) : "memory");
}

__global__ void __launch_bounds__(256) scatter2_kernel(
    const int* __restrict__ src, const int* __restrict__ dst,
    const float* __restrict__ hsrc, float* __restrict__ sum)
{
    int t = blockIdx.x * blockDim.x + threadIdx.x;
    int c = t & 15;
    int e = t >> 4;                 // [0, NE/2)
    int s0 = __ldg(src + e);
    int d0 = __ldg(dst + e);
    int s1 = __ldg(src + e + NE / 2);
    int d1 = __ldg(dst + e + NE / 2);
    float4 v0 = __ldg((const float4*)hsrc + (size_t)s0 * 16 + c);
    float4 v1 = __ldg((const float4*)hsrc + (size_t)s1 * 16 + c);
    red4(sum + (size_t)d0 * DD + c * 4, v0);
    red4(sum + (size_t)d1 * DD + c * 4, v1);
}

// ---------------------------------------------------------------------------
// combine: out[row,:] = act( sum_m scale_m(X_m[row,:]) @ W_m + bias )
// G pointers hold PRE-INVERTED degree (1/max(deg,1)).
// Inner loop uses fma.rn.f32x2: 8 packed FFMA2 per k instead of 16 FFMA.
// PROJ: additionally computes out2 = (result) @ Wp + bp (full tiles assumed).
// ---------------------------------------------------------------------------
template<int NMAT, bool ACT, bool PROJ>
__global__ void __launch_bounds__(256) combine_kernel(
    int nrows,
    const float* __restrict__ X0,
    const float* __restrict__ X1, const float* __restrict__ g1,
    const float* __restrict__ X2, const float* __restrict__ g2,
    const float* __restrict__ W0, const float* __restrict__ W0b,
    const float* __restrict__ W1,
    const float* __restrict__ W2,
    const float* __restrict__ bias0, const float* __restrict__ bias0b,
    float* __restrict__ out,
    const float* __restrict__ Wp, const float* __restrict__ bp,
    float* __restrict__ out2)
{
    __shared__ float Xs[DD][68];
    __shared__ float Ws[DD * DD];
    __shared__ float bs[DD];

    const int tid  = threadIdx.x;
    const int row0 = blockIdx.x * 64;

    if (tid < DD) {
        float b = bias0[tid];
        if (bias0b) b += bias0b[tid];
        bs[tid] = b;
    }

    u64 acc01[4], acc23[4];
#pragma unroll
    for (int r = 0; r < 4; ++r) { acc01[r] = 0ULL; acc23[r] = 0ULL; }

    const int lr = tid >> 2;
    const int lq = tid & 3;
    const int tr = tid >> 4;
    const int tc = tid & 15;
    const int  row_l  = row0 + lr;
    const bool lvalid = row_l < nrows;

#pragma unroll
    for (int m = 0; m < NMAT; ++m) {
        const float* X = (m == 0) ? X0 : ((m == 1) ? X1 : X2);
        const float* G = (m == 0) ? (const float*)nullptr : ((m == 1) ? g1 : g2);
        const float* W = (m == 0) ? W0 : ((m == 1) ? W1 : W2);

#pragma unroll
        for (int i = 0; i < 4; ++i) {
            float4 w = __ldg((const float4*)W + tid + i * 256);
            if (m == 0 && W0b != nullptr) {
                float4 w2 = __ldg((const float4*)W0b + tid + i * 256);
                w.x += w2.x; w.y += w2.y; w.z += w2.z; w.w += w2.w;
            }
            ((float4*)Ws)[tid + i * 256] = w;
        }

        float sc = 1.0f;
        if (G != nullptr && lvalid) sc = __ldg(G + row_l);   // pre-inverted
#pragma unroll
        for (int i = 0; i < 4; ++i) {
            float4 v = make_float4(0.f, 0.f, 0.f, 0.f);
            if (lvalid) v = __ldg((const float4*)(X + (size_t)row_l * DD) + lq * 4 + i);
            int k = lq * 16 + i * 4;
            Xs[k + 0][lr] = v.x * sc;
            Xs[k + 1][lr] = v.y * sc;
            Xs[k + 2][lr] = v.z * sc;
            Xs[k + 3][lr] = v.w * sc;
        }
        __syncthreads();

#pragma unroll 8
        for (int k = 0; k < DD; ++k) {
            float4 xv = *(const float4*)(&Xs[k][tr * 4]);
            float4 wv = *(const float4*)(&Ws[k * DD + tc * 4]);
            u64 w01 = f2pk(wv.x, wv.y);
            u64 w23 = f2pk(wv.z, wv.w);
            u64 x0 = f2pk(xv.x, xv.x);
            u64 x1 = f2pk(xv.y, xv.y);
            u64 x2 = f2pk(xv.z, xv.z);
            u64 x3 = f2pk(xv.w, xv.w);
            f2fma(acc01[0], x0, w01); f2fma(acc23[0], x0, w23);
            f2fma(acc01[1], x1, w01); f2fma(acc23[1], x1, w23);
            f2fma(acc01[2], x2, w01); f2fma(acc23[2], x2, w23);
            f2fma(acc01[3], x3, w01); f2fma(acc23[3], x3, w23);
        }
        __syncthreads();
    }

    // epilogue: unpack + bias (+act), store
    float vals[4][4];
#pragma unroll
    for (int r = 0; r < 4; ++r) {
        f2un(acc01[r], vals[r][0], vals[r][1]);
        f2un(acc23[r], vals[r][2], vals[r][3]);
#pragma unroll
        for (int j = 0; j < 4; ++j) {
            float o = vals[r][j] + bs[tc * 4 + j];
            if (ACT) o = o > 0.f ? o : 0.01f * o;
            vals[r][j] = o;
        }
        int row = row0 + tr * 4 + r;
        if (row < nrows) {
            float4 o = make_float4(vals[r][0], vals[r][1], vals[r][2], vals[r][3]);
            *((float4*)(out + (size_t)row * DD) + tc) = o;
        }
    }

    if (PROJ) {
        // second GEMM: out2 = vals @ Wp + bp  (tile is full: nrows % 64 == 0)
        // write result tile transposed into Xs (k-major)
#pragma unroll
        for (int r = 0; r < 4; ++r)
#pragma unroll
            for (int j = 0; j < 4; ++j)
                Xs[tc * 4 + j][tr * 4 + r] = vals[r][j];

#pragma unroll
        for (int i = 0; i < 4; ++i)
            ((float4*)Ws)[tid + i * 256] = __ldg((const float4*)Wp + tid + i * 256);
        if (tid < DD) bs[tid] = bp[tid];
        __syncthreads();

#pragma unroll
        for (int r = 0; r < 4; ++r) { acc01[r] = 0ULL; acc23[r] = 0ULL; }

#pragma unroll 8
        for (int k = 0; k < DD; ++k) {
            float4 xv = *(const float4*)(&Xs[k][tr * 4]);
            float4 wv = *(const float4*)(&Ws[k * DD + tc * 4]);
            u64 w01 = f2pk(wv.x, wv.y);
            u64 w23 = f2pk(wv.z, wv.w);
            u64 x0 = f2pk(xv.x, xv.x);
            u64 x1 = f2pk(xv.y, xv.y);
            u64 x2 = f2pk(xv.z, xv.z);
            u64 x3 = f2pk(xv.w, xv.w);
            f2fma(acc01[0], x0, w01); f2fma(acc23[0], x0, w23);
            f2fma(acc01[1], x1, w01); f2fma(acc23[1], x1, w23);
            f2fma(acc01[2], x2, w01); f2fma(acc23[2], x2, w23);
            f2fma(acc01[3], x3, w01); f2fma(acc23[3], x3, w23);
        }

#pragma unroll
        for (int r = 0; r < 4; ++r) {
            float a, b, c, d;
            f2un(acc01[r], a, b);
            f2un(acc23[r], c, d);
            int row = row0 + tr * 4 + r;
            float4 o = make_float4(a + bs[tc * 4 + 0], b + bs[tc * 4 + 1],
                                   c + bs[tc * 4 + 2], d + bs[tc * 4 + 3]);
            *((float4*)(out2 + (size_t)row * DD) + tc) = o;
        }
    }
}

// ---------------------------------------------------------------------------
extern "C" void kernel_launch(void* const* d_in, const int* in_sizes, int n_in,
                              void* d_out, int out_size)
{
    const float* features     = (const float*)d_in[0];
    const float* emb_client   = (const float*)d_in[1];
    const float* emb_merchant = (const float*)d_in[2];
    const float* Ws0  = (const float*)d_in[3];
    const float* Wn0  = (const float*)d_in[4];
    const float* b0   = (const float*)d_in[5];
    const float* Ws1  = (const float*)d_in[6];
    const float* Wn1  = (const float*)d_in[7];
    const float* b1   = (const float*)d_in[8];
    const float* Wout = (const float*)d_in[9];
    const float* bout = (const float*)d_in[10];
    const int* e0s = (const int*)d_in[11];
    const int* e0d = (const int*)d_in[12];
    const int* e1s = (const int*)d_in[13];
    const int* e1d = (const int*)d_in[14];
    const int* e2s = (const int*)d_in[15];
    const int* e2d = (const int*)d_in[16];
    const int* e3s = (const int*)d_in[17];
    const int* e3d = (const int*)d_in[18];
    float* out = (float*)d_out;

    float *sums, *degs, *htx, *hcl, *hme, *emb;
    cudaGetSymbolAddress((void**)&sums, g_sums);
    cudaGetSymbolAddress((void**)&degs, g_degs);
    cudaGetSymbolAddress((void**)&htx,  g_htx);
    cudaGetSymbolAddress((void**)&hcl,  g_hcl);
    cudaGetSymbolAddress((void**)&hme,  g_hme);
    cudaGetSymbolAddress((void**)&emb,  g_emb);

    float* emb_dst = (out_size >= (int)(2 * (size_t)NTX * DD)) ? out + (size_t)NTX * DD
                                                               : emb;

    // ---- zero accumulators ----
    zero_kernel<<<2048, 256>>>((float4*)sums, SUMS_LEN / 4);
    zero_kernel<<<512, 256>>>((float4*)degs, (size_t)DEGS_LEN / 4);

    // ---- degrees (once; reused by both layers), then invert ----
    const int dblocks = (NE + 255) / 256;
    deg_kernel<<<dblocks, 256>>>(e0d, degs + DEG0_OFF, NE);
    deg_kernel<<<dblocks, 256>>>(e2d, degs + DEG2_OFF, NE);
    deg_kernel<<<dblocks, 256>>>(e1d, degs + DEG1_OFF, NE);
    deg_kernel<<<dblocks, 256>>>(e3d, degs + DEG3_OFF, NE);
    inv_kernel<<<(DEGS_LEN + 255) / 256, 256>>>(degs, DEGS_LEN);

    const int sblocks = (NE / 2 * 16) / 256;  // 31250

    // ---- layer 0 aggregation ----
    scatter2_kernel<<<sblocks, 256>>>(e0s, e0d, emb_client,   sums + SUM0_OFF);
    scatter2_kernel<<<sblocks, 256>>>(e2s, e2d, emb_merchant, sums + SUM2_OFF);
    scatter2_kernel<<<sblocks, 256>>>(e1s, e1d, features,     sums + SUM1_OFF);
    scatter2_kernel<<<sblocks, 256>>>(e3s, e3d, features,     sums + SUM3_OFF);

    // ---- layer 0 combine (+ leaky_relu) ----
    combine_kernel<3, true, false><<<(NTX + 63) / 64, 256>>>(NTX,
        features,
        sums + SUM0_OFF, degs + DEG0_OFF,
        sums + SUM2_OFF, degs + DEG2_OFF,
        Ws0 + 0 * 4096, Ws0 + 2 * 4096,
        Wn0 + 0 * 4096, Wn0 + 2 * 4096,
        b0 + 0 * 64, b0 + 2 * 64,
        htx, nullptr, nullptr, nullptr);
    combine_kernel<2, true, false><<<(NCL + 63) / 64, 256>>>(NCL,
        emb_client,
        sums + SUM1_OFF, degs + DEG1_OFF,
        nullptr, nullptr,
        Ws0 + 1 * 4096, nullptr,
        Wn0 + 1 * 4096, nullptr,
        b0 + 1 * 64, nullptr,
        hcl, nullptr, nullptr, nullptr);
    combine_kernel<2, true, false><<<(NME + 63) / 64, 256>>>(NME,
        emb_merchant,
        sums + SUM3_OFF, degs + DEG3_OFF,
        nullptr, nullptr,
        Ws0 + 3 * 4096, nullptr,
        Wn0 + 3 * 4096, nullptr,
        b0 + 3 * 64, nullptr,
        hme, nullptr, nullptr, nullptr);

    // ---- layer 1: only tx output needed -> relations 0 and 2 ----
    zero_kernel<<<2048, 256>>>((float4*)sums, (size_t)2 * NTX * DD / 4);
    scatter2_kernel<<<sblocks, 256>>>(e0s, e0d, hcl, sums + SUM0_OFF);
    scatter2_kernel<<<sblocks, 256>>>(e2s, e2d, hme, sums + SUM2_OFF);

    // ---- layer 1 combine fused with output projection ----
    // emb -> emb_dst (d_out second half), emb @ Wout + bout -> out (first half)
    combine_kernel<3, false, true><<<(NTX + 63) / 64, 256>>>(NTX,
        htx,
        sums + SUM0_OFF, degs + DEG0_OFF,
        sums + SUM2_OFF, degs + DEG2_OFF,
        Ws1 + 0 * 4096, Ws1 + 2 * 4096,
        Wn1 + 0 * 4096, Wn1 + 2 * 4096,
        b1 + 0 * 64, b1 + 2 * 64,
        emb_dst, Wout, bout, out);

    // fallback: if out only holds the projection, nothing more to do;
    // if emb went to g_emb because out is small, copy what fits
    if (emb_dst == emb && out_size > (int)((size_t)NTX * DD)) {
        size_t extra = (size_t)out_size - (size_t)NTX * DD;
        if (extra > (size_t)NTX * DD) extra = (size_t)NTX * DD;
        cudaMemcpyAsync(out + (size_t)NTX * DD, emb, extra * sizeof(float),
                        cudaMemcpyDeviceToDevice);
    }
}

// round 4
// speedup vs baseline: 1.2817x; 1.1612x over previous
#include <cuda_runtime.h>
#include <cstdint>
#include <cstddef>

#define NTX 200000
#define NCL 100000
#define NME 20000
#define NE  1000000
#define DD  64

// global node index space (concatenated by destination segment):
//   [0, NTX)            rel0 dst (tx)        -> mean0
//   [NTX, 2NTX)         rel2 dst (tx)        -> mean2
//   [2NTX, 2NTX+NCL)    rel1 dst (client)    -> mean1
//   [.., +NME)          rel3 dst (merchant)  -> mean3
#define DEG0_OFF 0
#define DEG2_OFF (NTX)
#define DEG1_OFF (2*NTX)
#define DEG3_OFF (2*NTX+NCL)
#define DEGS_LEN (2*NTX+NCL+NME)          // 520000
#define NBLK_SCAN ((DEGS_LEN + 255)/256)  // 2032
#define NEDGE_TOT (4*NE)

#define SUM0_OFF ((size_t)DEG0_OFF*DD)
#define SUM2_OFF ((size_t)DEG2_OFF*DD)
#define SUM1_OFF ((size_t)DEG1_OFF*DD)
#define SUM3_OFF ((size_t)DEG3_OFF*DD)

__device__ float g_sums[(size_t)DEGS_LEN*DD];   // per-row neighbor MEANS
__device__ int   g_deg[DEGS_LEN];
__device__ int   g_rowptr[DEGS_LEN + 1];
__device__ int   g_cursor[DEGS_LEN];
__device__ float g_inv[DEGS_LEN];
__device__ int   g_bsum[2048];
__device__ int   g_bscan[2048];
__device__ int   g_srcidx[NEDGE_TOT];
__device__ float g_htx[(size_t)NTX*DD];
__device__ float g_hcl[(size_t)NCL*DD];
__device__ float g_hme[(size_t)NME*DD];
__device__ float g_emb[(size_t)NTX*DD];

// ---------------- packed fp32x2 helpers (Blackwell FFMA2) -------------------
typedef unsigned long long u64;
__device__ __forceinline__ u64 f2pk(float lo, float hi) {
    u64 r; asm("mov.b64 %0,{%1,%2};" : "=l"(r) : "f"(lo), "f"(hi)); return r;
}
__device__ __forceinline__ void f2fma(u64& d, u64 a, u64 b) {
    asm("fma.rn.f32x2 %0,%1,%2,%0;" : "+l"(d) : "l"(a), "l"(b));
}
__device__ __forceinline__ void f2un(u64 p, float& lo, float& hi) {
    asm("mov.b64 {%0,%1},%2;" : "=f"(lo), "=f"(hi) : "l"(p));
}

// ---------------------------------------------------------------------------
__global__ void zero_int_kernel(int* __restrict__ p, int n) {
    int i = blockIdx.x * blockDim.x + threadIdx.x;
    if (i < n) p[i] = 0;
}

// fused histogram over all 4 relations (4M threads)
__global__ void __launch_bounds__(256) hist4_kernel(
    const int* __restrict__ e0d, const int* __restrict__ e2d,
    const int* __restrict__ e1d, const int* __restrict__ e3d,
    int* __restrict__ deg)
{
    int t = blockIdx.x * blockDim.x + threadIdx.x;
    const int* dp; int off, e;
    if (t < NE)            { dp = e0d; off = DEG0_OFF; e = t; }
    else if (t < 2 * NE)   { dp = e2d; off = DEG2_OFF; e = t - NE; }
    else if (t < 3 * NE)   { dp = e1d; off = DEG1_OFF; e = t - 2 * NE; }
    else                   { dp = e3d; off = DEG3_OFF; e = t - 3 * NE; }
    atomicAdd(deg + off + __ldg(dp + e), 1);
}

// scan pass 1: per-block totals
__global__ void __launch_bounds__(256) scan_bsum_kernel(const int* __restrict__ deg,
                                                        int* __restrict__ bsum) {
    __shared__ int s[256];
    int tid = threadIdx.x;
    int i = blockIdx.x * 256 + tid;
    s[tid] = (i < DEGS_LEN) ? deg[i] : 0;
    __syncthreads();
#pragma unroll
    for (int o = 128; o > 0; o >>= 1) {
        if (tid < o) s[tid] += s[tid + o];
        __syncthreads();
    }
    if (tid == 0) bsum[blockIdx.x] = s[0];
}

// scan pass 2: exclusive scan of 2048 block sums, single block of 1024
__global__ void __launch_bounds__(1024) scan_top_kernel(const int* __restrict__ bsum,
                                                        int* __restrict__ bscan) {
    __shared__ int s[1024];
    int t = threadIdx.x;
    int a = bsum[2 * t], b = bsum[2 * t + 1];
    int pair = a + b;
    s[t] = pair;
    __syncthreads();
    for (int o = 1; o < 1024; o <<= 1) {
        int v = (t >= o) ? s[t - o] : 0;
        __syncthreads();
        s[t] += v;
        __syncthreads();
    }
    int base = s[t] - pair;                 // exclusive prefix of pair 2t
    bscan[2 * t]     = base;
    bscan[2 * t + 1] = base + a;
}

// scan pass 3: final rowptr/cursor/inv (+ sentinel)
__global__ void __launch_bounds__(256) scan_final_kernel(
    const int* __restrict__ deg, const int* __restrict__ bscan,
    int* __restrict__ rowptr, int* __restrict__ cursor, float* __restrict__ inv)
{
    __shared__ int s[256];
    int tid = threadIdx.x;
    int i = blockIdx.x * 256 + tid;
    int v = (i < DEGS_LEN) ? deg[i] : 0;
    s[tid] = v;
    __syncthreads();
    for (int o = 1; o < 256; o <<= 1) {
        int x = (tid >= o) ? s[tid - o] : 0;
        __syncthreads();
        s[tid] += x;
        __syncthreads();
    }
    if (i < DEGS_LEN) {
        int excl = bscan[blockIdx.x] + s[tid] - v;
        rowptr[i] = excl;
        cursor[i] = excl;
        inv[i] = 1.0f / fmaxf((float)v, 1.0f);
        if (i == DEGS_LEN - 1) rowptr[DEGS_LEN] = excl + v;
    }
}

// fused fill over all 4 relations: srcidx[pos] = src
__global__ void __launch_bounds__(256) fill4_kernel(
    const int* __restrict__ e0s, const int* __restrict__ e0d,
    const int* __restrict__ e2s, const int* __restrict__ e2d,
    const int* __restrict__ e1s, const int* __restrict__ e1d,
    const int* __restrict__ e3s, const int* __restrict__ e3d,
    int* __restrict__ cursor, int* __restrict__ srcidx)
{
    int t = blockIdx.x * blockDim.x + threadIdx.x;
    const int* sp; const int* dp; int off, e;
    if (t < NE)            { sp = e0s; dp = e0d; off = DEG0_OFF; e = t; }
    else if (t < 2 * NE)   { sp = e2s; dp = e2d; off = DEG2_OFF; e = t - NE; }
    else if (t < 3 * NE)   { sp = e1s; dp = e1d; off = DEG1_OFF; e = t - 2 * NE; }
    else                   { sp = e3s; dp = e3d; off = DEG3_OFF; e = t - 3 * NE; }
    int d = __ldg(dp + e);
    int s = __ldg(sp + e);
    int pos = atomicAdd(cursor + off + d, 1);
    srcidx[pos] = s;
}

// ---------------------------------------------------------------------------
// gather-reduce: 16 threads per row walk its src list, write mean once.
// L0 covers all DEGS_LEN rows; source table selected by segment.
// ---------------------------------------------------------------------------
__device__ __forceinline__ void gather_row(
    int i, int c, const float* __restrict__ hs,
    const int* __restrict__ rowptr, const int* __restrict__ srcidx,
    const float* __restrict__ inv, float* __restrict__ sums)
{
    int start = __ldg(rowptr + i);
    int end   = __ldg(rowptr + i + 1);
    float4 a0 = make_float4(0.f, 0.f, 0.f, 0.f);
    float4 a1 = make_float4(0.f, 0.f, 0.f, 0.f);
    int j = start;
    for (; j + 1 < end; j += 2) {
        int s0 = __ldg(srcidx + j);
        int s1 = __ldg(srcidx + j + 1);
        float4 v0 = __ldg((const float4*)hs + (size_t)s0 * 16 + c);
        float4 v1 = __ldg((const float4*)hs + (size_t)s1 * 16 + c);
        a0.x += v0.x; a0.y += v0.y; a0.z += v0.z; a0.w += v0.w;
        a1.x += v1.x; a1.y += v1.y; a1.z += v1.z; a1.w += v1.w;
    }
    if (j < end) {
        int s0 = __ldg(srcidx + j);
        float4 v0 = __ldg((const float4*)hs + (size_t)s0 * 16 + c);
        a0.x += v0.x; a0.y += v0.y; a0.z += v0.z; a0.w += v0.w;
    }
    float sc = __ldg(inv + i);
    float4 o = make_float4((a0.x + a1.x) * sc, (a0.y + a1.y) * sc,
                           (a0.z + a1.z) * sc, (a0.w + a1.w) * sc);
    *((float4*)sums + (size_t)i * 16 + c) = o;
}

__global__ void __launch_bounds__(256) gatherL0_kernel(
    const float* __restrict__ emb_client, const float* __restrict__ emb_merchant,
    const float* __restrict__ features,
    const int* __restrict__ rowptr, const int* __restrict__ srcidx,
    const float* __restrict__ inv, float* __restrict__ sums)
{
    int t = blockIdx.x * blockDim.x + threadIdx.x;   // DEGS_LEN*16 threads exactly
    int i = t >> 4;
    int c = t & 15;
    const float* hs = (i < NTX) ? emb_client
                    : (i < 2 * NTX) ? emb_merchant : features;
    gather_row(i, c, hs, rowptr, srcidx, inv, sums);
}

__global__ void __launch_bounds__(256) gatherL1_kernel(
    const float* __restrict__ hcl, const float* __restrict__ hme,
    const int* __restrict__ rowptr, const int* __restrict__ srcidx,
    const float* __restrict__ inv, float* __restrict__ sums)
{
    int t = blockIdx.x * blockDim.x + threadIdx.x;   // 2*NTX*16 threads exactly
    int i = t >> 4;
    int c = t & 15;
    const float* hs = (i < NTX) ? hcl : hme;
    gather_row(i, c, hs, rowptr, srcidx, inv, sums);
}

// ---------------------------------------------------------------------------
// combine: out[row,:] = act( sum_m X_m[row,:] @ W_m + bias )   (means pre-scaled)
// PROJ: additionally out2 = result @ Wp + bp (full tiles: nrows % 64 == 0)
// ---------------------------------------------------------------------------
template<int NMAT, bool ACT, bool PROJ>
__global__ void __launch_bounds__(256) combine_kernel(
    int nrows,
    const float* __restrict__ X0,
    const float* __restrict__ X1,
    const float* __restrict__ X2,
    const float* __restrict__ W0, const float* __restrict__ W0b,
    const float* __restrict__ W1,
    const float* __restrict__ W2,
    const float* __restrict__ bias0, const float* __restrict__ bias0b,
    float* __restrict__ out,
    const float* __restrict__ Wp, const float* __restrict__ bp,
    float* __restrict__ out2)
{
    __shared__ float Xs[DD][68];
    __shared__ float Ws[DD * DD];
    __shared__ float bs[DD];

    const int tid  = threadIdx.x;
    const int row0 = blockIdx.x * 64;

    if (tid < DD) {
        float b = bias0[tid];
        if (bias0b) b += bias0b[tid];
        bs[tid] = b;
    }

    u64 acc01[4], acc23[4];
#pragma unroll
    for (int r = 0; r < 4; ++r) { acc01[r] = 0ULL; acc23[r] = 0ULL; }

    const int lr = tid >> 2;
    const int lq = tid & 3;
    const int tr = tid >> 4;
    const int tc = tid & 15;
    const int  row_l  = row0 + lr;
    const bool lvalid = row_l < nrows;

#pragma unroll
    for (int m = 0; m < NMAT; ++m) {
        const float* X = (m == 0) ? X0 : ((m == 1) ? X1 : X2);
        const float* W = (m == 0) ? W0 : ((m == 1) ? W1 : W2);

#pragma unroll
        for (int i = 0; i < 4; ++i) {
            float4 w = __ldg((const float4*)W + tid + i * 256);
            if (m == 0 && W0b != nullptr) {
                float4 w2 = __ldg((const float4*)W0b + tid + i * 256);
                w.x += w2.x; w.y += w2.y; w.z += w2.z; w.w += w2.w;
            }
            ((float4*)Ws)[tid + i * 256] = w;
        }

#pragma unroll
        for (int i = 0; i < 4; ++i) {
            float4 v = make_float4(0.f, 0.f, 0.f, 0.f);
            if (lvalid) v = __ldg((const float4*)(X + (size_t)row_l * DD) + lq * 4 + i);
            int k = lq * 16 + i * 4;
            Xs[k + 0][lr] = v.x;
            Xs[k + 1][lr] = v.y;
            Xs[k + 2][lr] = v.z;
            Xs[k + 3][lr] = v.w;
        }
        __syncthreads();

#pragma unroll 8
        for (int k = 0; k < DD; ++k) {
            float4 xv = *(const float4*)(&Xs[k][tr * 4]);
            float4 wv = *(const float4*)(&Ws[k * DD + tc * 4]);
            u64 w01 = f2pk(wv.x, wv.y);
            u64 w23 = f2pk(wv.z, wv.w);
            u64 x0 = f2pk(xv.x, xv.x);
            u64 x1 = f2pk(xv.y, xv.y);
            u64 x2 = f2pk(xv.z, xv.z);
            u64 x3 = f2pk(xv.w, xv.w);
            f2fma(acc01[0], x0, w01); f2fma(acc23[0], x0, w23);
            f2fma(acc01[1], x1, w01); f2fma(acc23[1], x1, w23);
            f2fma(acc01[2], x2, w01); f2fma(acc23[2], x2, w23);
            f2fma(acc01[3], x3, w01); f2fma(acc23[3], x3, w23);
        }
        __syncthreads();
    }

    float vals[4][4];
#pragma unroll
    for (int r = 0; r < 4; ++r) {
        f2un(acc01[r], vals[r][0], vals[r][1]);
        f2un(acc23[r], vals[r][2], vals[r][3]);
#pragma unroll
        for (int j = 0; j < 4; ++j) {
            float o = vals[r][j] + bs[tc * 4 + j];
            if (ACT) o = o > 0.f ? o : 0.01f * o;
            vals[r][j] = o;
        }
        int row = row0 + tr * 4 + r;
        if (row < nrows) {
            float4 o = make_float4(vals[r][0], vals[r][1], vals[r][2], vals[r][3]);
            *((float4*)(out + (size_t)row * DD) + tc) = o;
        }
    }

    if (PROJ) {
#pragma unroll
        for (int r = 0; r < 4; ++r)
#pragma unroll
            for (int j = 0; j < 4; ++j)
                Xs[tc * 4 + j][tr * 4 + r] = vals[r][j];

#pragma unroll
        for (int i = 0; i < 4; ++i)
            ((float4*)Ws)[tid + i * 256] = __ldg((const float4*)Wp + tid + i * 256);
        if (tid < DD) bs[tid] = bp[tid];
        __syncthreads();

#pragma unroll
        for (int r = 0; r < 4; ++r) { acc01[r] = 0ULL; acc23[r] = 0ULL; }

#pragma unroll 8
        for (int k = 0; k < DD; ++k) {
            float4 xv = *(const float4*)(&Xs[k][tr * 4]);
            float4 wv = *(const float4*)(&Ws[k * DD + tc * 4]);
            u64 w01 = f2pk(wv.x, wv.y);
            u64 w23 = f2pk(wv.z, wv.w);
            u64 x0 = f2pk(xv.x, xv.x);
            u64 x1 = f2pk(xv.y, xv.y);
            u64 x2 = f2pk(xv.z, xv.z);
            u64 x3 = f2pk(xv.w, xv.w);
            f2fma(acc01[0], x0, w01); f2fma(acc23[0], x0, w23);
            f2fma(acc01[1], x1, w01); f2fma(acc23[1], x1, w23);
            f2fma(acc01[2], x2, w01); f2fma(acc23[2], x2, w23);
            f2fma(acc01[3], x3, w01); f2fma(acc23[3], x3, w23);
        }

#pragma unroll
        for (int r = 0; r < 4; ++r) {
            float a, b, c, d;
            f2un(acc01[r], a, b);
            f2un(acc23[r], c, d);
            int row = row0 + tr * 4 + r;
            float4 o = make_float4(a + bs[tc * 4 + 0], b + bs[tc * 4 + 1],
                                   c + bs[tc * 4 + 2], d + bs[tc * 4 + 3]);
            *((float4*)(out2 + (size_t)row * DD) + tc) = o;
        }
    }
}

// ---------------------------------------------------------------------------
extern "C" void kernel_launch(void* const* d_in, const int* in_sizes, int n_in,
                              void* d_out, int out_size)
{
    const float* features     = (const float*)d_in[0];
    const float* emb_client   = (const float*)d_in[1];
    const float* emb_merchant = (const float*)d_in[2];
    const float* Ws0  = (const float*)d_in[3];
    const float* Wn0  = (const float*)d_in[4];
    const float* b0   = (const float*)d_in[5];
    const float* Ws1  = (const float*)d_in[6];
    const float* Wn1  = (const float*)d_in[7];
    const float* b1   = (const float*)d_in[8];
    const float* Wout = (const float*)d_in[9];
    const float* bout = (const float*)d_in[10];
    const int* e0s = (const int*)d_in[11];
    const int* e0d = (const int*)d_in[12];
    const int* e1s = (const int*)d_in[13];
    const int* e1d = (const int*)d_in[14];
    const int* e2s = (const int*)d_in[15];
    const int* e2d = (const int*)d_in[16];
    const int* e3s = (const int*)d_in[17];
    const int* e3d = (const int*)d_in[18];
    float* out = (float*)d_out;

    float *sums, *inv, *htx, *hcl, *hme, *emb;
    int *deg, *rowptr, *cursor, *bsum, *bscan, *srcidx;
    cudaGetSymbolAddress((void**)&sums,   g_sums);
    cudaGetSymbolAddress((void**)&inv,    g_inv);
    cudaGetSymbolAddress((void**)&deg,    g_deg);
    cudaGetSymbolAddress((void**)&rowptr, g_rowptr);
    cudaGetSymbolAddress((void**)&cursor, g_cursor);
    cudaGetSymbolAddress((void**)&bsum,   g_bsum);
    cudaGetSymbolAddress((void**)&bscan,  g_bscan);
    cudaGetSymbolAddress((void**)&srcidx, g_srcidx);
    cudaGetSymbolAddress((void**)&htx,    g_htx);
    cudaGetSymbolAddress((void**)&hcl,    g_hcl);
    cudaGetSymbolAddress((void**)&hme,    g_hme);
    cudaGetSymbolAddress((void**)&emb,    g_emb);

    float* emb_dst = (out_size >= (int)(2 * (size_t)NTX * DD)) ? out + (size_t)NTX * DD
                                                               : emb;

    // ---- CSR build (reused by both layers) ----
    zero_int_kernel<<<NBLK_SCAN, 256>>>(deg, DEGS_LEN);
    zero_int_kernel<<<8, 256>>>(bsum, 2048);
    hist4_kernel<<<NEDGE_TOT / 256, 256>>>(e0d, e2d, e1d, e3d, deg);
    scan_bsum_kernel<<<NBLK_SCAN, 256>>>(deg, bsum);
    scan_top_kernel<<<1, 1024>>>(bsum, bscan);
    scan_final_kernel<<<NBLK_SCAN, 256>>>(deg, bscan, rowptr, cursor, inv);
    fill4_kernel<<<NEDGE_TOT / 256, 256>>>(e0s, e0d, e2s, e2d, e1s, e1d, e3s, e3d,
                                           cursor, srcidx);

    // ---- layer 0 aggregation: one fused gather over all 4 segments ----
    gatherL0_kernel<<<DEGS_LEN * 16 / 256, 256>>>(emb_client, emb_merchant, features,
                                                  rowptr, srcidx, inv, sums);

    // ---- layer 0 combine (+ leaky_relu) ----
    combine_kernel<3, true, false><<<(NTX + 63) / 64, 256>>>(NTX,
        features, sums + SUM0_OFF, sums + SUM2_OFF,
        Ws0 + 0 * 4096, Ws0 + 2 * 4096,
        Wn0 + 0 * 4096, Wn0 + 2 * 4096,
        b0 + 0 * 64, b0 + 2 * 64,
        htx, nullptr, nullptr, nullptr);
    combine_kernel<2, true, false><<<(NCL + 63) / 64, 256>>>(NCL,
        emb_client, sums + SUM1_OFF, nullptr,
        Ws0 + 1 * 4096, nullptr,
        Wn0 + 1 * 4096, nullptr,
        b0 + 1 * 64, nullptr,
        hcl, nullptr, nullptr, nullptr);
    combine_kernel<2, true, false><<<(NME + 63) / 64, 256>>>(NME,
        emb_merchant, sums + SUM3_OFF, nullptr,
        Ws0 + 3 * 4096, nullptr,
        Wn0 + 3 * 4096, nullptr,
        b0 + 3 * 64, nullptr,
        hme, nullptr, nullptr, nullptr);

    // ---- layer 1: only tx needed -> gather rel0/rel2 from hcl/hme ----
    gatherL1_kernel<<<2 * NTX * 16 / 256, 256>>>(hcl, hme, rowptr, srcidx, inv, sums);

    // ---- layer 1 combine fused with output projection ----
    combine_kernel<3, false, true><<<(NTX + 63) / 64, 256>>>(NTX,
        htx, sums + SUM0_OFF, sums + SUM2_OFF,
        Ws1 + 0 * 4096, Ws1 + 2 * 4096,
        Wn1 + 0 * 4096, Wn1 + 2 * 4096,
        b1 + 0 * 64, b1 + 2 * 64,
        emb_dst, Wout, bout, out);

    if (emb_dst == emb && out_size > (int)((size_t)NTX * DD)) {
        size_t extra = (size_t)out_size - (size_t)NTX * DD;
        if (extra > (size_t)NTX * DD) extra = (size_t)NTX * DD;
        cudaMemcpyAsync(out + (size_t)NTX * DD, emb, extra * sizeof(float),
                        cudaMemcpyDeviceToDevice);
    }
}

// round 6
// speedup vs baseline: 1.4511x; 1.1322x over previous
#include <cuda_runtime.h>
#include <cstdint>
#include <cstddef>

#define NTX 200000
#define NCL 100000
#define NME 20000
#define NE  1000000
#define DD  64

#define DEG0_OFF 0
#define DEG2_OFF (NTX)
#define DEG1_OFF (2*NTX)
#define DEG3_OFF (2*NTX+NCL)
#define DEGS_LEN (2*NTX+NCL+NME)          // 520000
#define NBLK_SCAN ((DEGS_LEN + 255)/256)  // 2032
#define NEDGE_TOT (4*NE)

#define SUM0_OFF ((size_t)DEG0_OFF*DD)
#define SUM2_OFF ((size_t)DEG2_OFF*DD)
#define SUM1_OFF ((size_t)DEG1_OFF*DD)
#define SUM3_OFF ((size_t)DEG3_OFF*DD)

// dynamic smem layout for combine_tc: Asm | Bsm | bs
#define ASM_U32 (64 * 33 * 4)             // 8448 u32 = 33792 B
#define BSM_U32 (64 * 33 * 2)             // 4224 u32 = 16896 B
#define SMEM_BYTES (ASM_U32 * 4 + BSM_U32 * 4 + 64 * 4)   // 50944 B

__device__ float g_sums[(size_t)DEGS_LEN*DD];   // per-row neighbor MEANS
__device__ int   g_deg[DEGS_LEN];
__device__ int   g_rowptr[DEGS_LEN + 1];
__device__ int   g_cursor[DEGS_LEN];
__device__ float g_inv[DEGS_LEN];
__device__ int   g_bsum[2048];
__device__ int   g_bscan[2048];
__device__ int   g_srcidx[NEDGE_TOT];
__device__ float g_htx[(size_t)NTX*DD];
__device__ float g_hcl[(size_t)NCL*DD];
__device__ float g_hme[(size_t)NME*DD];
__device__ float g_emb[(size_t)NTX*DD];

// ---------------------------------------------------------------------------
__global__ void zero_int_kernel(int* __restrict__ p, int n) {
    int i = blockIdx.x * blockDim.x + threadIdx.x;
    if (i < n) p[i] = 0;
}

__global__ void __launch_bounds__(256) hist4_kernel(
    const int* __restrict__ e0d, const int* __restrict__ e2d,
    const int* __restrict__ e1d, const int* __restrict__ e3d,
    int* __restrict__ deg)
{
    int t = blockIdx.x * blockDim.x + threadIdx.x;
    const int* dp; int off, e;
    if (t < NE)            { dp = e0d; off = DEG0_OFF; e = t; }
    else if (t < 2 * NE)   { dp = e2d; off = DEG2_OFF; e = t - NE; }
    else if (t < 3 * NE)   { dp = e1d; off = DEG1_OFF; e = t - 2 * NE; }
    else                   { dp = e3d; off = DEG3_OFF; e = t - 3 * NE; }
    atomicAdd(deg + off + __ldg(dp + e), 1);
}

__global__ void __launch_bounds__(256) scan_bsum_kernel(const int* __restrict__ deg,
                                                        int* __restrict__ bsum) {
    __shared__ int s[256];
    int tid = threadIdx.x;
    int i = blockIdx.x * 256 + tid;
    s[tid] = (i < DEGS_LEN) ? deg[i] : 0;
    __syncthreads();
#pragma unroll
    for (int o = 128; o > 0; o >>= 1) {
        if (tid < o) s[tid] += s[tid + o];
        __syncthreads();
    }
    if (tid == 0) bsum[blockIdx.x] = s[0];
}

__global__ void __launch_bounds__(1024) scan_top_kernel(const int* __restrict__ bsum,
                                                        int* __restrict__ bscan) {
    __shared__ int s[1024];
    int t = threadIdx.x;
    int a = bsum[2 * t], b = bsum[2 * t + 1];
    int pair = a + b;
    s[t] = pair;
    __syncthreads();
    for (int o = 1; o < 1024; o <<= 1) {
        int v = (t >= o) ? s[t - o] : 0;
        __syncthreads();
        s[t] += v;
        __syncthreads();
    }
    int base = s[t] - pair;
    bscan[2 * t]     = base;
    bscan[2 * t + 1] = base + a;
}

__global__ void __launch_bounds__(256) scan_final_kernel(
    const int* __restrict__ deg, const int* __restrict__ bscan,
    int* __restrict__ rowptr, int* __restrict__ cursor, float* __restrict__ inv)
{
    __shared__ int s[256];
    int tid = threadIdx.x;
    int i = blockIdx.x * 256 + tid;
    int v = (i < DEGS_LEN) ? deg[i] : 0;
    s[tid] = v;
    __syncthreads();
    for (int o = 1; o < 256; o <<= 1) {
        int x = (tid >= o) ? s[tid - o] : 0;
        __syncthreads();
        s[tid] += x;
        __syncthreads();
    }
    if (i < DEGS_LEN) {
        int excl = bscan[blockIdx.x] + s[tid] - v;
        rowptr[i] = excl;
        cursor[i] = excl;
        inv[i] = 1.0f / fmaxf((float)v, 1.0f);
        if (i == DEGS_LEN - 1) rowptr[DEGS_LEN] = excl + v;
    }
}

__global__ void __launch_bounds__(256) fill4_kernel(
    const int* __restrict__ e0s, const int* __restrict__ e0d,
    const int* __restrict__ e2s, const int* __restrict__ e2d,
    const int* __restrict__ e1s, const int* __restrict__ e1d,
    const int* __restrict__ e3s, const int* __restrict__ e3d,
    int* __restrict__ cursor, int* __restrict__ srcidx)
{
    int t = blockIdx.x * blockDim.x + threadIdx.x;
    const int* sp; const int* dp; int off, e;
    if (t < NE)            { sp = e0s; dp = e0d; off = DEG0_OFF; e = t; }
    else if (t < 2 * NE)   { sp = e2s; dp = e2d; off = DEG2_OFF; e = t - NE; }
    else if (t < 3 * NE)   { sp = e1s; dp = e1d; off = DEG1_OFF; e = t - 2 * NE; }
    else                   { sp = e3s; dp = e3d; off = DEG3_OFF; e = t - 3 * NE; }
    int d = __ldg(dp + e);
    int s = __ldg(sp + e);
    int pos = atomicAdd(cursor + off + d, 1);
    srcidx[pos] = s;
}

// ---------------------------------------------------------------------------
// gather-reduce: 16 threads per row, 4 independent accumulators
// ---------------------------------------------------------------------------
__device__ __forceinline__ void gather_row(
    int i, int c, const float* __restrict__ hs,
    const int* __restrict__ rowptr, const int* __restrict__ srcidx,
    const float* __restrict__ inv, float* __restrict__ sums)
{
    int start = __ldg(rowptr + i);
    int end   = __ldg(rowptr + i + 1);
    float4 a0 = make_float4(0.f, 0.f, 0.f, 0.f);
    float4 a1 = make_float4(0.f, 0.f, 0.f, 0.f);
    float4 a2 = make_float4(0.f, 0.f, 0.f, 0.f);
    float4 a3 = make_float4(0.f, 0.f, 0.f, 0.f);
    int j = start;
    for (; j + 3 < end; j += 4) {
        int s0 = __ldg(srcidx + j);
        int s1 = __ldg(srcidx + j + 1);
        int s2 = __ldg(srcidx + j + 2);
        int s3 = __ldg(srcidx + j + 3);
        float4 v0 = __ldg((const float4*)hs + (size_t)s0 * 16 + c);
        float4 v1 = __ldg((const float4*)hs + (size_t)s1 * 16 + c);
        float4 v2 = __ldg((const float4*)hs + (size_t)s2 * 16 + c);
        float4 v3 = __ldg((const float4*)hs + (size_t)s3 * 16 + c);
        a0.x += v0.x; a0.y += v0.y; a0.z += v0.z; a0.w += v0.w;
        a1.x += v1.x; a1.y += v1.y; a1.z += v1.z; a1.w += v1.w;
        a2.x += v2.x; a2.y += v2.y; a2.z += v2.z; a2.w += v2.w;
        a3.x += v3.x; a3.y += v3.y; a3.z += v3.z; a3.w += v3.w;
    }
    for (; j < end; ++j) {
        int s0 = __ldg(srcidx + j);
        float4 v0 = __ldg((const float4*)hs + (size_t)s0 * 16 + c);
        a0.x += v0.x; a0.y += v0.y; a0.z += v0.z; a0.w += v0.w;
    }
    float sc = __ldg(inv + i);
    float4 o = make_float4((a0.x + a1.x + a2.x + a3.x) * sc,
                           (a0.y + a1.y + a2.y + a3.y) * sc,
                           (a0.z + a1.z + a2.z + a3.z) * sc,
                           (a0.w + a1.w + a2.w + a3.w) * sc);
    *((float4*)sums + (size_t)i * 16 + c) = o;
}

__global__ void __launch_bounds__(256) gatherL0_kernel(
    const float* __restrict__ emb_client, const float* __restrict__ emb_merchant,
    const float* __restrict__ features,
    const int* __restrict__ rowptr, const int* __restrict__ srcidx,
    const float* __restrict__ inv, float* __restrict__ sums)
{
    int t = blockIdx.x * blockDim.x + threadIdx.x;
    int i = t >> 4;
    int c = t & 15;
    const float* hs = (i < NTX) ? emb_client
                    : (i < 2 * NTX) ? emb_merchant : features;
    gather_row(i, c, hs, rowptr, srcidx, inv, sums);
}

__global__ void __launch_bounds__(256) gatherL1_kernel(
    const float* __restrict__ hcl, const float* __restrict__ hme,
    const int* __restrict__ rowptr, const int* __restrict__ srcidx,
    const float* __restrict__ inv, float* __restrict__ sums)
{
    int t = blockIdx.x * blockDim.x + threadIdx.x;
    int i = t >> 4;
    int c = t & 15;
    const float* hs = (i < NTX) ? hcl : hme;
    gather_row(i, c, hs, rowptr, srcidx, inv, sums);
}

// ---------------------------------------------------------------------------
// tf32 tensor-core combine (dynamic smem: Asm | Bsm | bs)
// ---------------------------------------------------------------------------
__device__ __forceinline__ uint32_t tf32c(float x) {
    uint32_t u; asm("cvt.rna.tf32.f32 %0, %1;" : "=r"(u) : "f"(x)); return u;
}

__device__ __forceinline__ void mma8(float* c, const uint32_t* a, const uint32_t* b) {
    asm volatile("mma.sync.aligned.m16n8k8.row.col.f32.tf32.tf32.f32 "
                 "{%0,%1,%2,%3},{%4,%5,%6,%7},{%8,%9},{%0,%1,%2,%3};"
                 : "+f"(c[0]), "+f"(c[1]), "+f"(c[2]), "+f"(c[3])
                 : "r"(a[0]), "r"(a[1]), "r"(a[2]), "r"(a[3]),
                   "r"(b[0]), "r"(b[1]));
}

__device__ __forceinline__ int a_idx(int rl, int cc) {
    int m = rl >> 4, kc = cc >> 3;
    int lane = ((rl & 7) << 2) | (cc & 3);
    int i = ((cc >> 2) & 1) * 2 + ((rl >> 3) & 1);
    return ((m * 8 + kc) * 33 + lane) * 4 + i;
}
__device__ __forceinline__ int b_idx(int k, int n) {
    int nch = n >> 3, kc = k >> 3;
    int lane = ((n & 7) << 2) | (k & 3);
    int j = (k >> 2) & 1;
    return ((nch * 8 + kc) * 33 + lane) * 2 + j;
}

template<int NMAT, bool ACT, bool PROJ>
__global__ void __launch_bounds__(256) combine_tc_kernel(
    int nrows,
    const float* __restrict__ X0,
    const float* __restrict__ X1,
    const float* __restrict__ X2,
    const float* __restrict__ W0, const float* __restrict__ W0b,
    const float* __restrict__ W1,
    const float* __restrict__ W2,
    const float* __restrict__ bias0, const float* __restrict__ bias0b,
    float* __restrict__ out,
    const float* __restrict__ Wp, const float* __restrict__ bp,
    float* __restrict__ out2)
{
    extern __shared__ uint32_t smem_raw[];
    uint32_t* Asm = smem_raw;                  // ASM_U32
    uint32_t* Bsm = smem_raw + ASM_U32;        // BSM_U32
    float*    bs  = (float*)(smem_raw + ASM_U32 + BSM_U32);  // 64

    const int tid = threadIdx.x;
    const int warp = tid >> 5, lane = tid & 31;
    const int wm = warp >> 1, wn = warp & 1;
    const int row0 = blockIdx.x * 128;
    const int groupID = lane >> 2, tig = lane & 3;

    if (tid < 64) bs[tid] = bias0[tid] + (bias0b ? bias0b[tid] : 0.f);

    float c[2][4][4];
#pragma unroll
    for (int mm = 0; mm < 2; ++mm)
#pragma unroll
        for (int nn = 0; nn < 4; ++nn)
#pragma unroll
            for (int q = 0; q < 4; ++q) c[mm][nn][q] = 0.f;

#pragma unroll
    for (int m = 0; m < NMAT; ++m) {
        const float* X = (m == 0) ? X0 : ((m == 1) ? X1 : X2);
        const float* W = (m == 0) ? W0 : ((m == 1) ? W1 : W2);

#pragma unroll
        for (int i = 0; i < 4; ++i) {
            int f4 = tid + i * 256;
            float4 w = __ldg((const float4*)W + f4);
            if (m == 0 && W0b != nullptr) {
                float4 w2 = __ldg((const float4*)W0b + f4);
                w.x += w2.x; w.y += w2.y; w.z += w2.z; w.w += w2.w;
            }
            int k  = f4 >> 4;
            int n0 = (f4 & 15) * 4;
            Bsm[b_idx(k, n0 + 0)] = tf32c(w.x);
            Bsm[b_idx(k, n0 + 1)] = tf32c(w.y);
            Bsm[b_idx(k, n0 + 2)] = tf32c(w.z);
            Bsm[b_idx(k, n0 + 3)] = tf32c(w.w);
        }

#pragma unroll
        for (int i = 0; i < 8; ++i) {
            int f4 = tid + i * 256;
            int rl = f4 >> 4;
            int c0 = (f4 & 15) * 4;
            float4 v = make_float4(0.f, 0.f, 0.f, 0.f);
            if (row0 + rl < nrows)
                v = __ldg((const float4*)(X + (size_t)(row0 + rl) * DD) + (c0 >> 2));
            Asm[a_idx(rl, c0 + 0)] = tf32c(v.x);
            Asm[a_idx(rl, c0 + 1)] = tf32c(v.y);
            Asm[a_idx(rl, c0 + 2)] = tf32c(v.z);
            Asm[a_idx(rl, c0 + 3)] = tf32c(v.w);
        }
        __syncthreads();

#pragma unroll
        for (int kc = 0; kc < 8; ++kc) {
            uint32_t b[4][2];
#pragma unroll
            for (int nn = 0; nn < 4; ++nn) {
                uint2 t2 = *(const uint2*)(Bsm + (((wn * 4 + nn) * 8 + kc) * 33 + lane) * 2);
                b[nn][0] = t2.x; b[nn][1] = t2.y;
            }
#pragma unroll
            for (int mm = 0; mm < 2; ++mm) {
                uint4 t4 = *(const uint4*)(Asm + (((wm * 2 + mm) * 8 + kc) * 33 + lane) * 4);
                uint32_t a[4] = {t4.x, t4.y, t4.z, t4.w};
#pragma unroll
                for (int nn = 0; nn < 4; ++nn) mma8(c[mm][nn], a, b[nn]);
            }
        }
        __syncthreads();
    }

#pragma unroll
    for (int mm = 0; mm < 2; ++mm) {
#pragma unroll
        for (int nn = 0; nn < 4; ++nn) {
            int rA = row0 + (wm * 2 + mm) * 16 + groupID;
            int cb = (wn * 4 + nn) * 8 + tig * 2;
            float b0v = bs[cb], b1v = bs[cb + 1];
            float v00 = c[mm][nn][0] + b0v;
            float v01 = c[mm][nn][1] + b1v;
            float v10 = c[mm][nn][2] + b0v;
            float v11 = c[mm][nn][3] + b1v;
            if (ACT) {
                v00 = v00 > 0.f ? v00 : 0.01f * v00;
                v01 = v01 > 0.f ? v01 : 0.01f * v01;
                v10 = v10 > 0.f ? v10 : 0.01f * v10;
                v11 = v11 > 0.f ? v11 : 0.01f * v11;
            }
            c[mm][nn][0] = v00; c[mm][nn][1] = v01;
            c[mm][nn][2] = v10; c[mm][nn][3] = v11;
            if (rA < nrows) {
                float2 o = make_float2(v00, v01);
                *(float2*)(out + (size_t)rA * DD + cb) = o;
            }
            if (rA + 8 < nrows) {
                float2 o = make_float2(v10, v11);
                *(float2*)(out + (size_t)(rA + 8) * DD + cb) = o;
            }
        }
    }

    if (PROJ) {
        __syncthreads();

#pragma unroll
        for (int mm = 0; mm < 2; ++mm) {
#pragma unroll
            for (int nn = 0; nn < 4; ++nn) {
                int rl0 = (wm * 2 + mm) * 16 + groupID;
                int rl1 = rl0 + 8;
                int cb  = (wn * 4 + nn) * 8 + tig * 2;
                Asm[a_idx(rl0, cb)]     = tf32c(c[mm][nn][0]);
                Asm[a_idx(rl0, cb + 1)] = tf32c(c[mm][nn][1]);
                Asm[a_idx(rl1, cb)]     = tf32c(c[mm][nn][2]);
                Asm[a_idx(rl1, cb + 1)] = tf32c(c[mm][nn][3]);
            }
        }
#pragma unroll
        for (int i = 0; i < 4; ++i) {
            int f4 = tid + i * 256;
            float4 w = __ldg((const float4*)Wp + f4);
            int k  = f4 >> 4;
            int n0 = (f4 & 15) * 4;
            Bsm[b_idx(k, n0 + 0)] = tf32c(w.x);
            Bsm[b_idx(k, n0 + 1)] = tf32c(w.y);
            Bsm[b_idx(k, n0 + 2)] = tf32c(w.z);
            Bsm[b_idx(k, n0 + 3)] = tf32c(w.w);
        }
        if (tid < 64) bs[tid] = bp[tid];
        __syncthreads();

#pragma unroll
        for (int mm = 0; mm < 2; ++mm)
#pragma unroll
            for (int nn = 0; nn < 4; ++nn)
#pragma unroll
                for (int q = 0; q < 4; ++q) c[mm][nn][q] = 0.f;

#pragma unroll
        for (int kc = 0; kc < 8; ++kc) {
            uint32_t b[4][2];
#pragma unroll
            for (int nn = 0; nn < 4; ++nn) {
                uint2 t2 = *(const uint2*)(Bsm + (((wn * 4 + nn) * 8 + kc) * 33 + lane) * 2);
                b[nn][0] = t2.x; b[nn][1] = t2.y;
            }
#pragma unroll
            for (int mm = 0; mm < 2; ++mm) {
                uint4 t4 = *(const uint4*)(Asm + (((wm * 2 + mm) * 8 + kc) * 33 + lane) * 4);
                uint32_t a[4] = {t4.x, t4.y, t4.z, t4.w};
#pragma unroll
                for (int nn = 0; nn < 4; ++nn) mma8(c[mm][nn], a, b[nn]);
            }
        }

#pragma unroll
        for (int mm = 0; mm < 2; ++mm) {
#pragma unroll
            for (int nn = 0; nn < 4; ++nn) {
                int rA = row0 + (wm * 2 + mm) * 16 + groupID;
                int cb = (wn * 4 + nn) * 8 + tig * 2;
                float b0v = bs[cb], b1v = bs[cb + 1];
                if (rA < nrows) {
                    float2 o = make_float2(c[mm][nn][0] + b0v, c[mm][nn][1] + b1v);
                    *(float2*)(out2 + (size_t)rA * DD + cb) = o;
                }
                if (rA + 8 < nrows) {
                    float2 o = make_float2(c[mm][nn][2] + b0v, c[mm][nn][3] + b1v);
                    *(float2*)(out2 + (size_t)(rA + 8) * DD + cb) = o;
                }
            }
        }
    }
}

// ---------------------------------------------------------------------------
extern "C" void kernel_launch(void* const* d_in, const int* in_sizes, int n_in,
                              void* d_out, int out_size)
{
    const float* features     = (const float*)d_in[0];
    const float* emb_client   = (const float*)d_in[1];
    const float* emb_merchant = (const float*)d_in[2];
    const float* Ws0  = (const float*)d_in[3];
    const float* Wn0  = (const float*)d_in[4];
    const float* b0   = (const float*)d_in[5];
    const float* Ws1  = (const float*)d_in[6];
    const float* Wn1  = (const float*)d_in[7];
    const float* b1   = (const float*)d_in[8];
    const float* Wout = (const float*)d_in[9];
    const float* bout = (const float*)d_in[10];
    const int* e0s = (const int*)d_in[11];
    const int* e0d = (const int*)d_in[12];
    const int* e1s = (const int*)d_in[13];
    const int* e1d = (const int*)d_in[14];
    const int* e2s = (const int*)d_in[15];
    const int* e2d = (const int*)d_in[16];
    const int* e3s = (const int*)d_in[17];
    const int* e3d = (const int*)d_in[18];
    float* out = (float*)d_out;

    float *sums, *inv, *htx, *hcl, *hme, *emb;
    int *deg, *rowptr, *cursor, *bsum, *bscan, *srcidx;
    cudaGetSymbolAddress((void**)&sums,   g_sums);
    cudaGetSymbolAddress((void**)&inv,    g_inv);
    cudaGetSymbolAddress((void**)&deg,    g_deg);
    cudaGetSymbolAddress((void**)&rowptr, g_rowptr);
    cudaGetSymbolAddress((void**)&cursor, g_cursor);
    cudaGetSymbolAddress((void**)&bsum,   g_bsum);
    cudaGetSymbolAddress((void**)&bscan,  g_bscan);
    cudaGetSymbolAddress((void**)&srcidx, g_srcidx);
    cudaGetSymbolAddress((void**)&htx,    g_htx);
    cudaGetSymbolAddress((void**)&hcl,    g_hcl);
    cudaGetSymbolAddress((void**)&hme,    g_hme);
    cudaGetSymbolAddress((void**)&emb,    g_emb);

    // opt-in to >48KB dynamic smem for each instantiation (idempotent host call)
    cudaFuncSetAttribute(combine_tc_kernel<3, true,  false>,
                         cudaFuncAttributeMaxDynamicSharedMemorySize, SMEM_BYTES);
    cudaFuncSetAttribute(combine_tc_kernel<2, true,  false>,
                         cudaFuncAttributeMaxDynamicSharedMemorySize, SMEM_BYTES);
    cudaFuncSetAttribute(combine_tc_kernel<3, false, true>,
                         cudaFuncAttributeMaxDynamicSharedMemorySize, SMEM_BYTES);

    float* emb_dst = (out_size >= (int)(2 * (size_t)NTX * DD)) ? out + (size_t)NTX * DD
                                                               : emb;

    // ---- CSR build (reused by both layers) ----
    zero_int_kernel<<<NBLK_SCAN, 256>>>(deg, DEGS_LEN);
    zero_int_kernel<<<8, 256>>>(bsum, 2048);
    hist4_kernel<<<NEDGE_TOT / 256, 256>>>(e0d, e2d, e1d, e3d, deg);
    scan_bsum_kernel<<<NBLK_SCAN, 256>>>(deg, bsum);
    scan_top_kernel<<<1, 1024>>>(bsum, bscan);
    scan_final_kernel<<<NBLK_SCAN, 256>>>(deg, bscan, rowptr, cursor, inv);
    fill4_kernel<<<NEDGE_TOT / 256, 256>>>(e0s, e0d, e2s, e2d, e1s, e1d, e3s, e3d,
                                           cursor, srcidx);

    // ---- layer 0 aggregation ----
    gatherL0_kernel<<<DEGS_LEN * 16 / 256, 256>>>(emb_client, emb_merchant, features,
                                                  rowptr, srcidx, inv, sums);

    // ---- layer 0 combine (+ leaky_relu) ----
    combine_tc_kernel<3, true, false><<<(NTX + 127) / 128, 256, SMEM_BYTES>>>(NTX,
        features, sums + SUM0_OFF, sums + SUM2_OFF,
        Ws0 + 0 * 4096, Ws0 + 2 * 4096,
        Wn0 + 0 * 4096, Wn0 + 2 * 4096,
        b0 + 0 * 64, b0 + 2 * 64,
        htx, nullptr, nullptr, nullptr);
    combine_tc_kernel<2, true, false><<<(NCL + 127) / 128, 256, SMEM_BYTES>>>(NCL,
        emb_client, sums + SUM1_OFF, nullptr,
        Ws0 + 1 * 4096, nullptr,
        Wn0 + 1 * 4096, nullptr,
        b0 + 1 * 64, nullptr,
        hcl, nullptr, nullptr, nullptr);
    combine_tc_kernel<2, true, false><<<(NME + 127) / 128, 256, SMEM_BYTES>>>(NME,
        emb_merchant, sums + SUM3_OFF, nullptr,
        Ws0 + 3 * 4096, nullptr,
        Wn0 + 3 * 4096, nullptr,
        b0 + 3 * 64, nullptr,
        hme, nullptr, nullptr, nullptr);

    // ---- layer 1: only tx needed -> gather rel0/rel2 from hcl/hme ----
    gatherL1_kernel<<<2 * NTX * 16 / 256, 256>>>(hcl, hme, rowptr, srcidx, inv, sums);

    // ---- layer 1 combine fused with output projection ----
    combine_tc_kernel<3, false, true><<<(NTX + 127) / 128, 256, SMEM_BYTES>>>(NTX,
        htx, sums + SUM0_OFF, sums + SUM2_OFF,
        Ws1 + 0 * 4096, Ws1 + 2 * 4096,
        Wn1 + 0 * 4096, Wn1 + 2 * 4096,
        b1 + 0 * 64, b1 + 2 * 64,
        emb_dst, Wout, bout, out);

    if (emb_dst == emb && out_size > (int)((size_t)NTX * DD)) {
        size_t extra = (size_t)out_size - (size_t)NTX * DD;
        if (extra > (size_t)NTX * DD) extra = (size_t)NTX * DD;
        cudaMemcpyAsync(out + (size_t)NTX * DD, emb, extra * sizeof(float),
                        cudaMemcpyDeviceToDevice);
    }
}